// round 12
// baseline (speedup 1.0000x reference)
#include <cuda_runtime.h>
#include <cuda_fp16.h>

#define N_SRC 100000
#define N_DST 20000
#define N_EDGE 1250000
#define D 64
#define NEG_SLOPE 0.2f
#define BIN_CAP 256
#define N_TILES 6250          // 100000 / 16 rows per mma tile

typedef unsigned int u32;

// ---------------- scratch -----------------------------------------------------
__device__ __half2 g_hh[(size_t)N_SRC * 32]; // h = x @ W, fp16 (col pair per lane)
__device__ float g_asrc[N_SRC];              // h . att_src (fp32-exact from fp32 x)
__device__ float g_adst[N_DST];              // x[res_n_id] . (W @ att_dst), fp32
__device__ float g_wasrc[D];                 // W @ att_src
__device__ float g_wadst[D];                 // W @ att_dst
__device__ int   g_deg[N_DST];               // zeroed at end of k_agg (replay-safe)
__device__ int2  g_sbin[(size_t)N_DST * BIN_CAP];  // (src, p_bits), static bins

// ---------------- helpers -----------------------------------------------------
__device__ __forceinline__ u32 f2h2(float a, float b) {
    __half2 h = __floats2half2_rn(a, b);
    return *reinterpret_cast<u32*>(&h);
}
__device__ __forceinline__ void mma16816(float& c0, float& c1, float& c2, float& c3,
                                         u32 a0, u32 a1, u32 a2, u32 a3,
                                         u32 b0, u32 b1) {
    asm volatile(
        "mma.sync.aligned.m16n8k16.row.col.f32.f16.f16.f32 "
        "{%0,%1,%2,%3}, {%4,%5,%6,%7}, {%8,%9}, {%0,%1,%2,%3};"
        : "+f"(c0), "+f"(c1), "+f"(c2), "+f"(c3)
        : "r"(a0), "r"(a1), "r"(a2), "r"(a3), "r"(b0), "r"(b1));
}

// ---------------- K0: wasrc = W @ att_src, wadst = W @ att_dst ------------------
__global__ void k_wvec(const float* __restrict__ W,
                       const float* __restrict__ att_src,
                       const float* __restrict__ att_dst) {
    int k = threadIdx.x;
    if (k < D) {
        float s0 = 0.f, s1 = 0.f;
        #pragma unroll 8
        for (int c = 0; c < D; ++c) {
            float wv = W[k * D + c];
            s0 += wv * att_src[c];
            s1 += wv * att_dst[c];
        }
        g_wasrc[k] = s0;
        g_wadst[k] = s1;
    }
}

// ---------------- K1: tensor-core GEMM h = x@W (+ exact fp32 a_src) -----------
__global__ __launch_bounds__(256) void k_mma(const float* __restrict__ x,
                                             const float* __restrict__ W) {
    __shared__ __half  WhT[64 * 72];        // W^T, stride 72 halves (conflict-free B)
    __shared__ float   ws[64];              // wasrc
    __shared__ __half2 hs[8][16 * 36];      // epilogue transpose, stride 36 (c-free)

    const int tid  = threadIdx.x;
    const int lane = tid & 31;
    const int w    = tid >> 5;
    const int g    = lane >> 2;             // groupID (row within tile)
    const int q    = lane & 3;              // thread-in-group

    for (int i = tid; i < 64 * 64; i += 256) {
        int k = i >> 6, c = i & 63;
        WhT[c * 72 + k] = __float2half(W[i]);
    }
    if (tid < 64) ws[tid] = g_wasrc[tid];
    __syncthreads();

    const int tile = blockIdx.x * 8 + w;
    if (tile < N_TILES) {
        const int r0 = tile * 16;
        const float2* __restrict__ x2 = (const float2*)x;

        float acc[8][4];
        #pragma unroll
        for (int n = 0; n < 8; ++n) {
            acc[n][0] = 0.f; acc[n][1] = 0.f; acc[n][2] = 0.f; acc[n][3] = 0.f;
        }
        float plo = 0.f, phi = 0.f;

        #pragma unroll
        for (int kk = 0; kk < 4; ++kk) {
            const int ci = kk * 8 + q;
            float2 v0 = x2[(size_t)(r0 + g) * 32 + ci];
            float2 v1 = x2[(size_t)(r0 + g + 8) * 32 + ci];
            float2 v2 = x2[(size_t)(r0 + g) * 32 + ci + 4];
            float2 v3 = x2[(size_t)(r0 + g + 8) * 32 + ci + 4];

            float2 wsa = *(const float2*)&ws[kk * 16 + 2 * q];
            float2 wsb = *(const float2*)&ws[kk * 16 + 2 * q + 8];
            plo += v0.x * wsa.x + v0.y * wsa.y + v2.x * wsb.x + v2.y * wsb.y;
            phi += v1.x * wsa.x + v1.y * wsa.y + v3.x * wsb.x + v3.y * wsb.y;

            u32 a0 = f2h2(v0.x, v0.y);
            u32 a1 = f2h2(v1.x, v1.y);
            u32 a2 = f2h2(v2.x, v2.y);
            u32 a3 = f2h2(v3.x, v3.y);

            #pragma unroll
            for (int n = 0; n < 8; ++n) {
                const __half* bp = &WhT[(n * 8 + g) * 72 + kk * 16 + 2 * q];
                u32 b0 = *(const u32*)bp;
                u32 b1 = *(const u32*)(bp + 8);
                mma16816(acc[n][0], acc[n][1], acc[n][2], acc[n][3],
                         a0, a1, a2, a3, b0, b1);
            }
        }

        plo += __shfl_xor_sync(0xffffffffu, plo, 1);
        plo += __shfl_xor_sync(0xffffffffu, plo, 2);
        phi += __shfl_xor_sync(0xffffffffu, phi, 1);
        phi += __shfl_xor_sync(0xffffffffu, phi, 2);
        if (q == 0) {
            g_asrc[r0 + g]     = plo;
            g_asrc[r0 + 8 + g] = phi;
        }

        #pragma unroll
        for (int n = 0; n < 8; ++n) {
            hs[w][g * 36 + 4 * n + q]       = __floats2half2_rn(acc[n][0], acc[n][1]);
            hs[w][(g + 8) * 36 + 4 * n + q] = __floats2half2_rn(acc[n][2], acc[n][3]);
        }
        __syncwarp();
        #pragma unroll
        for (int r = 0; r < 16; ++r)
            g_hh[(size_t)(r0 + r) * 32 + lane] = hs[w][r * 36 + lane];
    }
}

// ---------------- K2: a_dst[j] = x[res_n_id[j]] . wadst (fp32-exact) -----------
__global__ __launch_bounds__(256) void k_adst(const float* __restrict__ x,
                                              const int* __restrict__ res_n_id) {
    const int lane = threadIdx.x & 31;
    const int w    = threadIdx.x >> 5;
    const int j    = blockIdx.x * 8 + w;     // 2500 * 8 = 20000
    if (j >= N_DST) return;
    int rid = res_n_id[j];
    float2 xv = ((const float2*)x)[(size_t)rid * 32 + lane];
    float2 wv = ((const float2*)g_wadst)[lane];
    float p = xv.x * wv.x + xv.y * wv.y;
    #pragma unroll
    for (int d = 16; d > 0; d >>= 1) p += __shfl_xor_sync(0xffffffffu, p, d);
    if (lane == 0) g_adst[j] = p;
}

// ---------------- K3: edge pass, 4 edges/thread (latency-bound -> MLP) ---------
// Per-thread issue order: 4 independent atomics first (depend only on d),
// then 8 gathers, then compute + scatter. ~4x memory-level parallelism.
__global__ __launch_bounds__(256) void k_edges(const int* __restrict__ edge_src,
                                               const int* __restrict__ edge_dst) {
    int i = (blockIdx.x * blockDim.x + threadIdx.x) * 4;
    if (i >= N_EDGE) return;                  // N_EDGE % 4 == 0, int4 aligned
    int4 s4 = *(const int4*)&edge_src[i];
    int4 d4 = *(const int4*)&edge_dst[i];

    int r0 = atomicAdd(&g_deg[d4.x], 1);
    int r1 = atomicAdd(&g_deg[d4.y], 1);
    int r2 = atomicAdd(&g_deg[d4.z], 1);
    int r3 = atomicAdd(&g_deg[d4.w], 1);

    float as0 = g_asrc[s4.x], as1 = g_asrc[s4.y];
    float as2 = g_asrc[s4.z], as3 = g_asrc[s4.w];
    float ad0 = g_adst[d4.x], ad1 = g_adst[d4.y];
    float ad2 = g_adst[d4.z], ad3 = g_adst[d4.w];

    float e0 = as0 + ad0; e0 = (e0 > 0.f) ? e0 : NEG_SLOPE * e0;
    float e1 = as1 + ad1; e1 = (e1 > 0.f) ? e1 : NEG_SLOPE * e1;
    float e2 = as2 + ad2; e2 = (e2 > 0.f) ? e2 : NEG_SLOPE * e2;
    float e3 = as3 + ad3; e3 = (e3 > 0.f) ? e3 : NEG_SLOPE * e3;

    g_sbin[((size_t)d4.x << 8) + r0] = make_int2(s4.x, __float_as_int(__expf(e0)));
    g_sbin[((size_t)d4.y << 8) + r1] = make_int2(s4.y, __float_as_int(__expf(e1)));
    g_sbin[((size_t)d4.z << 8) + r2] = make_int2(s4.z, __float_as_int(__expf(e2)));
    g_sbin[((size_t)d4.w << 8) + r3] = make_int2(s4.w, __float_as_int(__expf(e3)));
}

// ---------------- K4: per-dst weighted aggregation (fp16 h gather) -------------
__global__ __launch_bounds__(256) void k_agg(float* __restrict__ out,
                                             const float* __restrict__ bias) {
    const int lane = threadIdx.x & 31;
    const int w    = threadIdx.x >> 5;
    const int j    = blockIdx.x * 8 + w;
    if (j >= N_DST) return;

    const size_t start = (size_t)j << 8;
    const int deg = g_deg[j];
    const size_t end = start + deg;

    float s = 0.f;
    float2 acc = make_float2(0.f, 0.f);

    size_t i = start;
    for (; i + 4 <= end; i += 4) {
        int2 e0 = g_sbin[i];
        int2 e1 = g_sbin[i + 1];
        int2 e2 = g_sbin[i + 2];
        int2 e3 = g_sbin[i + 3];
        float2 h0 = __half22float2(g_hh[(size_t)e0.x * 32 + lane]);
        float2 h1 = __half22float2(g_hh[(size_t)e1.x * 32 + lane]);
        float2 hc = __half22float2(g_hh[(size_t)e2.x * 32 + lane]);
        float2 h3 = __half22float2(g_hh[(size_t)e3.x * 32 + lane]);
        float p0 = __int_as_float(e0.y), p1 = __int_as_float(e1.y);
        float p2 = __int_as_float(e2.y), p3 = __int_as_float(e3.y);
        s += (p0 + p1) + (p2 + p3);
        acc.x += p0 * h0.x + p1 * h1.x + p2 * hc.x + p3 * h3.x;
        acc.y += p0 * h0.y + p1 * h1.y + p2 * hc.y + p3 * h3.y;
    }
    for (; i < end; ++i) {
        int2 e0 = g_sbin[i];
        float2 h0 = __half22float2(g_hh[(size_t)e0.x * 32 + lane]);
        float p0 = __int_as_float(e0.y);
        s += p0;
        acc.x += p0 * h0.x;
        acc.y += p0 * h0.y;
    }

    float inv = 1.f / (s + 1e-16f);
    float2 b2 = ((const float2*)bias)[lane];
    ((float2*)out)[(size_t)j * 32 + lane] =
        make_float2(acc.x * inv + b2.x, acc.y * inv + b2.y);

    if (lane == 0) g_deg[j] = 0;   // replay-safe reset
}

// ---------------- launch --------------------------------------------------------
extern "C" void kernel_launch(void* const* d_in, const int* in_sizes, int n_in,
                              void* d_out, int out_size) {
    const float* x        = (const float*)d_in[0];
    const int*   res_n_id = (const int*)  d_in[1];
    const int*   edge_src = (const int*)  d_in[2];
    const int*   edge_dst = (const int*)  d_in[3];
    const float* W        = (const float*)d_in[4];
    const float* att_src  = (const float*)d_in[5];
    const float* att_dst  = (const float*)d_in[6];
    const float* bias     = (const float*)d_in[7];
    float* out            = (float*)d_out;

    k_wvec <<<1, 64>>>(W, att_src, att_dst);
    k_mma  <<<(N_TILES + 7) / 8, 256>>>(x, W);                        // 782
    k_adst <<<N_DST / 8, 256>>>(x, res_n_id);                         // 2500
    k_edges<<<(N_EDGE / 4 + 255) / 256, 256>>>(edge_src, edge_dst);   // 1221
    k_agg  <<<N_DST / 8, 256>>>(out, bias);                           // 2500
}